// round 12
// baseline (speedup 1.0000x reference)
#include <cuda_runtime.h>
#include <cuda_fp16.h>
#include <math.h>

#define NN 50000
#define EE 800000
#define SLOTS 64   // max real in-degree supported (Poisson(16): P(>=64) ~ 5e-19/node)

// -------- static device scratch (no allocations allowed) --------
__device__ __half d_buf1h[(size_t)NN * 256];  // [XL | XR] layer 1, fp16
__device__ __half d_H[(size_t)NN * 128];      // elu output of layer 1, fp16 (GEMM2 input)
__device__ __half d_buf2h[(size_t)NN * 128];  // [HL | HR] layer 2, fp16
__device__ __half d_Bt1h[256 * 128];          // transposed [Wl1|Wr1] as half: Bt[c][k]
__device__ __half d_Bt2h[128 * 128];          // transposed [Wl2|Wr2] as half
__device__ int    d_cur[NN];                  // per-node real-edge count / cursor
__device__ int    d_csrsrc[(size_t)NN * SLOTS + 1];  // fixed-stride adjacency (+1 pad)

// -------- init: zero cursors + convert/transpose both weight blocks --------
__global__ void k_init(const float* __restrict__ Wl1, const float* __restrict__ Wr1,
                       const float* __restrict__ Wl2, const float* __restrict__ Wr2) {
    int idx = blockIdx.x * 256 + threadIdx.x;
    if (idx < NN) d_cur[idx] = 0;
    if (idx < 256 * 128) {
        int c = idx >> 7, k = idx & 127;
        d_Bt1h[idx] = __float2half(c < 128 ? Wl1[k * 128 + c] : Wr1[k * 128 + (c - 128)]);
    }
    if (idx < 128 * 128) {
        int c = idx >> 7, k = idx & 127;
        d_Bt2h[idx] = __float2half(c < 64 ? Wl2[k * 64 + c] : Wr2[k * 64 + (c - 64)]);
    }
}

// -------- direct scatter: no count, no scan (int4 vectorized) --------
__global__ void k_scatter(const int* __restrict__ ei) {
    int t = blockIdx.x * 256 + threadIdx.x;
    if (t * 4 >= EE) return;
    int4 s4 = *(const int4*)&ei[t * 4];
    int4 d4 = *(const int4*)&ei[EE + t * 4];
    d_csrsrc[d4.x * SLOTS + atomicAdd(&d_cur[d4.x], 1)] = s4.x;
    d_csrsrc[d4.y * SLOTS + atomicAdd(&d_cur[d4.y], 1)] = s4.y;
    d_csrsrc[d4.z * SLOTS + atomicAdd(&d_cur[d4.z], 1)] = s4.z;
    d_csrsrc[d4.w * SLOTS + atomicAdd(&d_cur[d4.w], 1)] = s4.w;
}

// -------- fp16 tensor-core GEMM (mma.m16n8k16), templated A dtype --------
// C[n x mC] = A[n x 128] @ Bt^T, Bt is [mC][128] half row-major.
// Block tile 128x64, 8 warps (4m x 2n), warp tile 32x32, K staged in 64-slabs.
// Smem holds half2 words at stride KW=36: bank = (4r + kp) mod 32, conflict-free frags.
#define KW 36

__device__ __forceinline__ void mma16(float* d, const unsigned* a, const unsigned* b) {
    asm("mma.sync.aligned.m16n8k16.row.col.f32.f16.f16.f32 "
        "{%0,%1,%2,%3}, {%4,%5,%6,%7}, {%8,%9}, {%0,%1,%2,%3};"
        : "+f"(d[0]), "+f"(d[1]), "+f"(d[2]), "+f"(d[3])
        : "r"(a[0]), "r"(a[1]), "r"(a[2]), "r"(a[3]), "r"(b[0]), "r"(b[1]));
}

template <typename TIN>
__global__ void k_gemm_h(const TIN* __restrict__ A, const __half* __restrict__ Bt,
                         __half* __restrict__ C, int n, int mC) {
    __shared__ unsigned As[128 * KW];  // half2 words: As[r][kp], kp = k/2 within slab
    __shared__ unsigned Bs[64 * KW];
    const int t    = threadIdx.x;
    const int lane = t & 31;
    const int w    = t >> 5;
    const int wr   = w & 3;
    const int wc   = w >> 2;
    const int gid  = lane >> 2;
    const int tig  = lane & 3;
    const int row0 = blockIdx.x * 128;
    const int col0 = blockIdx.y * 64;

    float acc[2][4][4];
#pragma unroll
    for (int mt = 0; mt < 2; ++mt)
#pragma unroll
        for (int nt = 0; nt < 4; ++nt)
#pragma unroll
            for (int i = 0; i < 4; ++i) acc[mt][nt][i] = 0.f;

    for (int ks = 0; ks < 128; ks += 64) {
        __syncthreads();
        {   // A slab: 128 rows x 64 halves; thread: row t>>1, half-offset (t&1)*32
            int r  = t >> 1;
            int kb = (t & 1) * 32;
            bool valid = (row0 + r) < n;
            unsigned* dstp = &As[r * KW + (t & 1) * 16];
            if constexpr (sizeof(TIN) == 4) {
                const float* Ar = (const float*)A + (size_t)(row0 + r) * 128 + ks + kb;
#pragma unroll
                for (int j = 0; j < 4; ++j) {
                    float4 v0 = valid ? *(const float4*)(Ar + j * 8)
                                      : make_float4(0.f, 0.f, 0.f, 0.f);
                    float4 v1 = valid ? *(const float4*)(Ar + j * 8 + 4)
                                      : make_float4(0.f, 0.f, 0.f, 0.f);
                    __half2 h0 = __floats2half2_rn(v0.x, v0.y);
                    __half2 h1 = __floats2half2_rn(v0.z, v0.w);
                    __half2 h2 = __floats2half2_rn(v1.x, v1.y);
                    __half2 h3 = __floats2half2_rn(v1.z, v1.w);
                    *(uint4*)(dstp + j * 4) =
                        make_uint4(*(unsigned*)&h0, *(unsigned*)&h1,
                                   *(unsigned*)&h2, *(unsigned*)&h3);
                }
            } else {
                const __half* Ar = (const __half*)A + (size_t)(row0 + r) * 128 + ks + kb;
#pragma unroll
                for (int j = 0; j < 4; ++j) {
                    uint4 v = valid ? *(const uint4*)(Ar + j * 8)
                                    : make_uint4(0u, 0u, 0u, 0u);
                    *(uint4*)(dstp + j * 4) = v;
                }
            }
        }
        {   // B slab: 64 cols x 64 halves; thread: col t>>2, half-offset (t&3)*16
            int c  = t >> 2;
            const __half* Br = Bt + (size_t)(col0 + c) * 128 + ks + (t & 3) * 16;
            unsigned* dstp = &Bs[c * KW + (t & 3) * 8];
#pragma unroll
            for (int j = 0; j < 2; ++j)
                *(uint4*)(dstp + j * 4) = *(const uint4*)(Br + j * 8);
        }
        __syncthreads();
#pragma unroll
        for (int kp = 0; kp < 32; kp += 8) {   // one k16 MMA step per 8 half2 words
            unsigned a[2][4], b[4][2];
#pragma unroll
            for (int mt = 0; mt < 2; ++mt) {
                int r = wr * 32 + mt * 16 + gid;
                a[mt][0] = As[r * KW + kp + tig];
                a[mt][1] = As[(r + 8) * KW + kp + tig];
                a[mt][2] = As[r * KW + kp + tig + 4];
                a[mt][3] = As[(r + 8) * KW + kp + tig + 4];
            }
#pragma unroll
            for (int nt = 0; nt < 4; ++nt) {
                int c = wc * 32 + nt * 8 + gid;
                b[nt][0] = Bs[c * KW + kp + tig];
                b[nt][1] = Bs[c * KW + kp + tig + 4];
            }
#pragma unroll
            for (int mt = 0; mt < 2; ++mt)
#pragma unroll
                for (int nt = 0; nt < 4; ++nt)
                    mma16(acc[mt][nt], a[mt], b[nt]);
        }
    }

#pragma unroll
    for (int mt = 0; mt < 2; ++mt) {
        int r = row0 + wr * 32 + mt * 16 + gid;
        int cbase = col0 + wc * 32 + tig * 2;
#pragma unroll
        for (int nt = 0; nt < 4; ++nt) {
            if (r < n) {
                __half2 h = __floats2half2_rn(acc[mt][nt][0], acc[mt][nt][1]);
                *(__half2*)&C[(size_t)r * mC + cbase + nt * 8] = h;
            }
            if (r + 8 < n) {
                __half2 h = __floats2half2_rn(acc[mt][nt][2], acc[mt][nt][3]);
                *(__half2*)&C[(size_t)(r + 8) * mC + cbase + nt * 8] = h;
            }
        }
    }
}

// -------- Layer 1: warp per dst; self-loop seeds the online softmax --------
__global__ void k_gat1(const float* __restrict__ att1, const float* __restrict__ b1) {
    int warp = (blockIdx.x * blockDim.x + threadIdx.x) >> 5;
    int lane = threadIdx.x & 31;
    if (warp >= NN) return;
    int dst = warp;
    uint2 rl = *(const uint2*)&d_buf1h[(size_t)dst * 256 + lane * 4];        // xl[dst]
    uint2 rr = *(const uint2*)&d_buf1h[(size_t)dst * 256 + 128 + lane * 4];  // xr[dst]
    float2 xl01 = __half22float2(*(__half2*)&rl.x);
    float2 xl23 = __half22float2(*(__half2*)&rl.y);
    float2 xr01 = __half22float2(*(__half2*)&rr.x);
    float2 xr23 = __half22float2(*(__half2*)&rr.y);
    float4 at = *(const float4*)&att1[lane * 4];

    // self-loop: src = dst
    float e0 = xl01.x + xr01.x; e0 = e0 > 0.f ? e0 : 0.2f * e0;
    float e1 = xl01.y + xr01.y; e1 = e1 > 0.f ? e1 : 0.2f * e1;
    float e2 = xl23.x + xr23.x; e2 = e2 > 0.f ? e2 : 0.2f * e2;
    float e3 = xl23.y + xr23.y; e3 = e3 > 0.f ? e3 : 0.2f * e3;
    float p = e0 * at.x + e1 * at.y + e2 * at.z + e3 * at.w;
    p += __shfl_xor_sync(0xffffffffu, p, 1);
    p += __shfl_xor_sync(0xffffffffu, p, 2);
    float m = p, den = 1.f;
    float4 acc = make_float4(xl01.x, xl01.y, xl23.x, xl23.y);

    int cnt = d_cur[dst];
    long base = (long)dst * SLOTS;
    int s = d_csrsrc[base];
    for (int i = 0; i < cnt; ++i) {
        int sn = d_csrsrc[base + i + 1];  // within slot region (cnt < SLOTS) or pad
        uint2 raw = *(const uint2*)&d_buf1h[(size_t)s * 256 + lane * 4];
        float2 lo = __half22float2(*(__half2*)&raw.x);
        float2 hi = __half22float2(*(__half2*)&raw.y);
        e0 = lo.x + xr01.x; e0 = e0 > 0.f ? e0 : 0.2f * e0;
        e1 = lo.y + xr01.y; e1 = e1 > 0.f ? e1 : 0.2f * e1;
        e2 = hi.x + xr23.x; e2 = e2 > 0.f ? e2 : 0.2f * e2;
        e3 = hi.y + xr23.y; e3 = e3 > 0.f ? e3 : 0.2f * e3;
        p = e0 * at.x + e1 * at.y + e2 * at.z + e3 * at.w;
        p += __shfl_xor_sync(0xffffffffu, p, 1);
        p += __shfl_xor_sync(0xffffffffu, p, 2);
        float nm = fmaxf(m, p);
        float sc = __expf(m - nm);
        float wgt = __expf(p - nm);
        den = den * sc + wgt;
        acc.x = acc.x * sc + wgt * lo.x;
        acc.y = acc.y * sc + wgt * lo.y;
        acc.z = acc.z * sc + wgt * hi.x;
        acc.w = acc.w * sc + wgt * hi.y;
        m = nm;
        s = sn;
    }
    float inv = 1.f / den;
    float4 bb = *(const float4*)&b1[lane * 4];
    float v0 = acc.x * inv + bb.x; v0 = v0 > 0.f ? v0 : expm1f(v0);
    float v1 = acc.y * inv + bb.y; v1 = v1 > 0.f ? v1 : expm1f(v1);
    float v2 = acc.z * inv + bb.z; v2 = v2 > 0.f ? v2 : expm1f(v2);
    float v3 = acc.w * inv + bb.w; v3 = v3 > 0.f ? v3 : expm1f(v3);
    __half2 h0 = __floats2half2_rn(v0, v1);
    __half2 h1 = __floats2half2_rn(v2, v3);
    *(uint2*)&d_H[(size_t)dst * 128 + lane * 4] =
        make_uint2(*(unsigned*)&h0, *(unsigned*)&h1);
}

// -------- Layer 2: warp per dst; self-loop seed + log_softmax --------
__global__ void k_gat2(const float* __restrict__ att2, const float* __restrict__ b2,
                       float* __restrict__ out) {
    int warp = (blockIdx.x * blockDim.x + threadIdx.x) >> 5;
    int lane = threadIdx.x & 31;
    if (warp >= NN) return;
    int dst = warp;
    unsigned rl = *(const unsigned*)&d_buf2h[(size_t)dst * 128 + lane * 2];       // hl[dst]
    unsigned rr = *(const unsigned*)&d_buf2h[(size_t)dst * 128 + 64 + lane * 2];  // hr[dst]
    float2 hl_d = __half22float2(*(__half2*)&rl);
    float2 hr   = __half22float2(*(__half2*)&rr);
    float2 a2 = *(const float2*)&att2[lane * 2];

    // self-loop
    float e0 = hl_d.x + hr.x; e0 = e0 > 0.f ? e0 : 0.2f * e0;
    float e1 = hl_d.y + hr.y; e1 = e1 > 0.f ? e1 : 0.2f * e1;
    float p = e0 * a2.x + e1 * a2.y;
#pragma unroll
    for (int off = 16; off >= 1; off >>= 1)
        p += __shfl_xor_sync(0xffffffffu, p, off);
    float m = p, den = 1.f;
    float2 acc = hl_d;

    int cnt = d_cur[dst];
    long base = (long)dst * SLOTS;
    int s = d_csrsrc[base];
    for (int i = 0; i < cnt; ++i) {
        int sn = d_csrsrc[base + i + 1];
        unsigned raw = *(const unsigned*)&d_buf2h[(size_t)s * 128 + lane * 2];
        float2 hl = __half22float2(*(__half2*)&raw);
        e0 = hl.x + hr.x; e0 = e0 > 0.f ? e0 : 0.2f * e0;
        e1 = hl.y + hr.y; e1 = e1 > 0.f ? e1 : 0.2f * e1;
        p = e0 * a2.x + e1 * a2.y;
#pragma unroll
        for (int off = 16; off >= 1; off >>= 1)
            p += __shfl_xor_sync(0xffffffffu, p, off);
        float nm = fmaxf(m, p);
        float sc = __expf(m - nm);
        float wgt = __expf(p - nm);
        den = den * sc + wgt;
        acc.x = acc.x * sc + wgt * hl.x;
        acc.y = acc.y * sc + wgt * hl.y;
        m = nm;
        s = sn;
    }
    float inv = 1.f / den;
    float o0 = acc.x * inv + b2[lane * 2];
    float o1 = acc.y * inv + b2[lane * 2 + 1];
    float mx = fmaxf(o0, o1);
#pragma unroll
    for (int off = 16; off >= 1; off >>= 1)
        mx = fmaxf(mx, __shfl_xor_sync(0xffffffffu, mx, off));
    float se = __expf(o0 - mx) + __expf(o1 - mx);
#pragma unroll
    for (int off = 16; off >= 1; off >>= 1)
        se += __shfl_xor_sync(0xffffffffu, se, off);
    float lse = mx + logf(se);
    out[(size_t)dst * 64 + lane * 2]     = o0 - lse;
    out[(size_t)dst * 64 + lane * 2 + 1] = o1 - lse;
}

// -------- launch (fork-join: scatter || GEMM1) --------
static cudaStream_t g_s1 = nullptr;
static cudaEvent_t  g_evA = nullptr, g_evB = nullptr;

extern "C" void kernel_launch(void* const* d_in, const int* in_sizes, int n_in,
                              void* d_out, int out_size) {
    const float* x    = (const float*)d_in[0];
    const int*   ei   = (const int*)d_in[1];
    const float* Wl1  = (const float*)d_in[2];
    const float* Wr1  = (const float*)d_in[3];
    const float* att1 = (const float*)d_in[4];
    const float* b1   = (const float*)d_in[5];
    const float* Wl2  = (const float*)d_in[6];
    const float* Wr2  = (const float*)d_in[7];
    const float* att2 = (const float*)d_in[8];
    const float* b2   = (const float*)d_in[9];
    float* out = (float*)d_out;

    if (!g_s1) {  // one-time host-object creation (no device memory)
        cudaStreamCreateWithFlags(&g_s1, cudaStreamNonBlocking);
        cudaEventCreateWithFlags(&g_evA, cudaEventDisableTiming);
        cudaEventCreateWithFlags(&g_evB, cudaEventDisableTiming);
    }

    __half *pBuf1h = nullptr, *pBuf2h = nullptr, *pH = nullptr;
    __half *pBt1 = nullptr, *pBt2 = nullptr;
    cudaGetSymbolAddress((void**)&pBuf1h, d_buf1h);
    cudaGetSymbolAddress((void**)&pH, d_H);
    cudaGetSymbolAddress((void**)&pBuf2h, d_buf2h);
    cudaGetSymbolAddress((void**)&pBt1, d_Bt1h);
    cudaGetSymbolAddress((void**)&pBt2, d_Bt2h);

    const int nb_nodes = (NN + 255) / 256;       // covers NN and 32768 transpose
    const int nb_edge4 = (EE / 4 + 255) / 256;   // 782

    // init: cursors = 0, weight transpose+fp16 convert
    k_init<<<nb_nodes, 256>>>(Wl1, Wr1, Wl2, Wr2);
    cudaEventRecord(g_evA, 0);

    // side stream: GEMM1 (needs Bt1 + x), concurrent with scatter
    cudaStreamWaitEvent(g_s1, g_evA, 0);
    {
        dim3 g1((NN + 127) / 128, 4);
        k_gemm_h<float><<<g1, 256, 0, g_s1>>>(x, pBt1, pBuf1h, NN, 256);
    }
    cudaEventRecord(g_evB, g_s1);

    // origin stream: direct adjacency scatter (no count/scan)
    k_scatter<<<nb_edge4, 256>>>(ei);

    // join, then layer 1 aggregate -> GEMM2 -> layer 2 aggregate
    cudaStreamWaitEvent(0, g_evB, 0);
    k_gat1<<<(NN + 7) / 8, 256>>>(att1, b1);
    {
        dim3 g2((NN + 127) / 128, 2);
        k_gemm_h<__half><<<g2, 256>>>(pH, pBt2, pBuf2h, NN, 128);
    }
    k_gat2<<<(NN + 7) / 8, 256>>>(att2, b2, out);
}

// round 13
// speedup vs baseline: 1.0024x; 1.0024x over previous
#include <cuda_runtime.h>
#include <cuda_fp16.h>
#include <math.h>

#define NN 50000
#define EE 800000
#define SLOTS 64   // max real in-degree supported (Poisson(16): P(>=64) ~ 5e-19/node)

// -------- static device scratch (no allocations allowed) --------
__device__ __half d_buf1h[(size_t)NN * 256];  // [XL | XR] layer 1, fp16
__device__ __half d_H[(size_t)NN * 128];      // elu output of layer 1, fp16 (GEMM2 input)
__device__ __half d_buf2h[(size_t)NN * 128];  // [HL | HR] layer 2, fp16
__device__ __half d_Bt1h[256 * 128];          // transposed [Wl1|Wr1] as half: Bt[c][k]
__device__ __half d_Bt2h[128 * 128];          // transposed [Wl2|Wr2] as half
__device__ int    d_cur[NN];                  // per-node real-edge count / cursor
__device__ int    d_csrsrc[(size_t)NN * SLOTS + 1];  // fixed-stride adjacency (+1 pad)

// -------- init: zero cursors + convert/transpose both weight blocks --------
__global__ void k_init(const float* __restrict__ Wl1, const float* __restrict__ Wr1,
                       const float* __restrict__ Wl2, const float* __restrict__ Wr2) {
    int idx = blockIdx.x * 256 + threadIdx.x;
    if (idx < NN) d_cur[idx] = 0;
    if (idx < 256 * 128) {
        int c = idx >> 7, k = idx & 127;
        d_Bt1h[idx] = __float2half(c < 128 ? Wl1[k * 128 + c] : Wr1[k * 128 + (c - 128)]);
    }
    if (idx < 128 * 128) {
        int c = idx >> 7, k = idx & 127;
        d_Bt2h[idx] = __float2half(c < 64 ? Wl2[k * 64 + c] : Wr2[k * 64 + (c - 64)]);
    }
}

// -------- direct scatter: no count, no scan (int4 vectorized) --------
__global__ void k_scatter(const int* __restrict__ ei) {
    int t = blockIdx.x * 256 + threadIdx.x;
    if (t * 4 >= EE) return;
    int4 s4 = *(const int4*)&ei[t * 4];
    int4 d4 = *(const int4*)&ei[EE + t * 4];
    d_csrsrc[d4.x * SLOTS + atomicAdd(&d_cur[d4.x], 1)] = s4.x;
    d_csrsrc[d4.y * SLOTS + atomicAdd(&d_cur[d4.y], 1)] = s4.y;
    d_csrsrc[d4.z * SLOTS + atomicAdd(&d_cur[d4.z], 1)] = s4.z;
    d_csrsrc[d4.w * SLOTS + atomicAdd(&d_cur[d4.w], 1)] = s4.w;
}

// -------- fp16 tensor-core GEMM (mma.m16n8k16), templated A dtype --------
// C[n x mC] = A[n x 128] @ Bt^T, Bt is [mC][128] half row-major.
// Block tile 128x64, 8 warps (4m x 2n), warp tile 32x32, K staged in 64-slabs.
// Smem holds half2 words at stride KW=36: bank = (4r + kp) mod 32, conflict-free frags.
#define KW 36

__device__ __forceinline__ void mma16(float* d, const unsigned* a, const unsigned* b) {
    asm("mma.sync.aligned.m16n8k16.row.col.f32.f16.f16.f32 "
        "{%0,%1,%2,%3}, {%4,%5,%6,%7}, {%8,%9}, {%0,%1,%2,%3};"
        : "+f"(d[0]), "+f"(d[1]), "+f"(d[2]), "+f"(d[3])
        : "r"(a[0]), "r"(a[1]), "r"(a[2]), "r"(a[3]), "r"(b[0]), "r"(b[1]));
}

template <typename TIN>
__global__ void k_gemm_h(const TIN* __restrict__ A, const __half* __restrict__ Bt,
                         __half* __restrict__ C, int n, int mC) {
    __shared__ unsigned As[128 * KW];  // half2 words: As[r][kp], kp = k/2 within slab
    __shared__ unsigned Bs[64 * KW];
    const int t    = threadIdx.x;
    const int lane = t & 31;
    const int w    = t >> 5;
    const int wr   = w & 3;
    const int wc   = w >> 2;
    const int gid  = lane >> 2;
    const int tig  = lane & 3;
    const int row0 = blockIdx.x * 128;
    const int col0 = blockIdx.y * 64;

    float acc[2][4][4];
#pragma unroll
    for (int mt = 0; mt < 2; ++mt)
#pragma unroll
        for (int nt = 0; nt < 4; ++nt)
#pragma unroll
            for (int i = 0; i < 4; ++i) acc[mt][nt][i] = 0.f;

    for (int ks = 0; ks < 128; ks += 64) {
        __syncthreads();
        {   // A slab: 128 rows x 64 halves; thread: row t>>1, half-offset (t&1)*32
            int r  = t >> 1;
            int kb = (t & 1) * 32;
            bool valid = (row0 + r) < n;
            unsigned* dstp = &As[r * KW + (t & 1) * 16];
            if constexpr (sizeof(TIN) == 4) {
                const float* Ar = (const float*)A + (size_t)(row0 + r) * 128 + ks + kb;
#pragma unroll
                for (int j = 0; j < 4; ++j) {
                    float4 v0 = valid ? *(const float4*)(Ar + j * 8)
                                      : make_float4(0.f, 0.f, 0.f, 0.f);
                    float4 v1 = valid ? *(const float4*)(Ar + j * 8 + 4)
                                      : make_float4(0.f, 0.f, 0.f, 0.f);
                    __half2 h0 = __floats2half2_rn(v0.x, v0.y);
                    __half2 h1 = __floats2half2_rn(v0.z, v0.w);
                    __half2 h2 = __floats2half2_rn(v1.x, v1.y);
                    __half2 h3 = __floats2half2_rn(v1.z, v1.w);
                    *(uint4*)(dstp + j * 4) =
                        make_uint4(*(unsigned*)&h0, *(unsigned*)&h1,
                                   *(unsigned*)&h2, *(unsigned*)&h3);
                }
            } else {
                const __half* Ar = (const __half*)A + (size_t)(row0 + r) * 128 + ks + kb;
#pragma unroll
                for (int j = 0; j < 4; ++j) {
                    uint4 v = valid ? *(const uint4*)(Ar + j * 8)
                                    : make_uint4(0u, 0u, 0u, 0u);
                    *(uint4*)(dstp + j * 4) = v;
                }
            }
        }
        {   // B slab: 64 cols x 64 halves; thread: col t>>2, half-offset (t&3)*16
            int c  = t >> 2;
            const __half* Br = Bt + (size_t)(col0 + c) * 128 + ks + (t & 3) * 16;
            unsigned* dstp = &Bs[c * KW + (t & 3) * 8];
#pragma unroll
            for (int j = 0; j < 2; ++j)
                *(uint4*)(dstp + j * 4) = *(const uint4*)(Br + j * 8);
        }
        __syncthreads();
#pragma unroll
        for (int kp = 0; kp < 32; kp += 8) {   // one k16 MMA step per 8 half2 words
            unsigned a[2][4], b[4][2];
#pragma unroll
            for (int mt = 0; mt < 2; ++mt) {
                int r = wr * 32 + mt * 16 + gid;
                a[mt][0] = As[r * KW + kp + tig];
                a[mt][1] = As[(r + 8) * KW + kp + tig];
                a[mt][2] = As[r * KW + kp + tig + 4];
                a[mt][3] = As[(r + 8) * KW + kp + tig + 4];
            }
#pragma unroll
            for (int nt = 0; nt < 4; ++nt) {
                int c = wc * 32 + nt * 8 + gid;
                b[nt][0] = Bs[c * KW + kp + tig];
                b[nt][1] = Bs[c * KW + kp + tig + 4];
            }
#pragma unroll
            for (int mt = 0; mt < 2; ++mt)
#pragma unroll
                for (int nt = 0; nt < 4; ++nt)
                    mma16(acc[mt][nt], a[mt], b[nt]);
        }
    }

#pragma unroll
    for (int mt = 0; mt < 2; ++mt) {
        int r = row0 + wr * 32 + mt * 16 + gid;
        int cbase = col0 + wc * 32 + tig * 2;
#pragma unroll
        for (int nt = 0; nt < 4; ++nt) {
            if (r < n) {
                __half2 h = __floats2half2_rn(acc[mt][nt][0], acc[mt][nt][1]);
                *(__half2*)&C[(size_t)r * mC + cbase + nt * 8] = h;
            }
            if (r + 8 < n) {
                __half2 h = __floats2half2_rn(acc[mt][nt][2], acc[mt][nt][3]);
                *(__half2*)&C[(size_t)(r + 8) * mC + cbase + nt * 8] = h;
            }
        }
    }
}

// -------- Layer 1: warp per dst; self-loop seeds the online softmax --------
__global__ void k_gat1(const float* __restrict__ att1, const float* __restrict__ b1) {
    int warp = (blockIdx.x * blockDim.x + threadIdx.x) >> 5;
    int lane = threadIdx.x & 31;
    if (warp >= NN) return;
    int dst = warp;
    uint2 rl = *(const uint2*)&d_buf1h[(size_t)dst * 256 + lane * 4];        // xl[dst]
    uint2 rr = *(const uint2*)&d_buf1h[(size_t)dst * 256 + 128 + lane * 4];  // xr[dst]
    float2 xl01 = __half22float2(*(__half2*)&rl.x);
    float2 xl23 = __half22float2(*(__half2*)&rl.y);
    float2 xr01 = __half22float2(*(__half2*)&rr.x);
    float2 xr23 = __half22float2(*(__half2*)&rr.y);
    float4 at = *(const float4*)&att1[lane * 4];

    // self-loop: src = dst
    float e0 = xl01.x + xr01.x; e0 = e0 > 0.f ? e0 : 0.2f * e0;
    float e1 = xl01.y + xr01.y; e1 = e1 > 0.f ? e1 : 0.2f * e1;
    float e2 = xl23.x + xr23.x; e2 = e2 > 0.f ? e2 : 0.2f * e2;
    float e3 = xl23.y + xr23.y; e3 = e3 > 0.f ? e3 : 0.2f * e3;
    float p = e0 * at.x + e1 * at.y + e2 * at.z + e3 * at.w;
    p += __shfl_xor_sync(0xffffffffu, p, 1);
    p += __shfl_xor_sync(0xffffffffu, p, 2);
    float m = p, den = 1.f;
    float4 acc = make_float4(xl01.x, xl01.y, xl23.x, xl23.y);

    int cnt = d_cur[dst];
    long base = (long)dst * SLOTS;
    int s = d_csrsrc[base];
    for (int i = 0; i < cnt; ++i) {
        int sn = d_csrsrc[base + i + 1];  // within slot region (cnt < SLOTS) or pad
        uint2 raw = *(const uint2*)&d_buf1h[(size_t)s * 256 + lane * 4];
        float2 lo = __half22float2(*(__half2*)&raw.x);
        float2 hi = __half22float2(*(__half2*)&raw.y);
        e0 = lo.x + xr01.x; e0 = e0 > 0.f ? e0 : 0.2f * e0;
        e1 = lo.y + xr01.y; e1 = e1 > 0.f ? e1 : 0.2f * e1;
        e2 = hi.x + xr23.x; e2 = e2 > 0.f ? e2 : 0.2f * e2;
        e3 = hi.y + xr23.y; e3 = e3 > 0.f ? e3 : 0.2f * e3;
        p = e0 * at.x + e1 * at.y + e2 * at.z + e3 * at.w;
        p += __shfl_xor_sync(0xffffffffu, p, 1);
        p += __shfl_xor_sync(0xffffffffu, p, 2);
        float nm = fmaxf(m, p);
        float sc = __expf(m - nm);
        float wgt = __expf(p - nm);
        den = den * sc + wgt;
        acc.x = acc.x * sc + wgt * lo.x;
        acc.y = acc.y * sc + wgt * lo.y;
        acc.z = acc.z * sc + wgt * hi.x;
        acc.w = acc.w * sc + wgt * hi.y;
        m = nm;
        s = sn;
    }
    float inv = 1.f / den;
    float4 bb = *(const float4*)&b1[lane * 4];
    float v0 = acc.x * inv + bb.x; v0 = v0 > 0.f ? v0 : expm1f(v0);
    float v1 = acc.y * inv + bb.y; v1 = v1 > 0.f ? v1 : expm1f(v1);
    float v2 = acc.z * inv + bb.z; v2 = v2 > 0.f ? v2 : expm1f(v2);
    float v3 = acc.w * inv + bb.w; v3 = v3 > 0.f ? v3 : expm1f(v3);
    __half2 h0 = __floats2half2_rn(v0, v1);
    __half2 h1 = __floats2half2_rn(v2, v3);
    *(uint2*)&d_H[(size_t)dst * 128 + lane * 4] =
        make_uint2(*(unsigned*)&h0, *(unsigned*)&h1);
}

// -------- Layer 2: warp per dst; self-loop seed + log_softmax --------
__global__ void k_gat2(const float* __restrict__ att2, const float* __restrict__ b2,
                       float* __restrict__ out) {
    int warp = (blockIdx.x * blockDim.x + threadIdx.x) >> 5;
    int lane = threadIdx.x & 31;
    if (warp >= NN) return;
    int dst = warp;
    unsigned rl = *(const unsigned*)&d_buf2h[(size_t)dst * 128 + lane * 2];       // hl[dst]
    unsigned rr = *(const unsigned*)&d_buf2h[(size_t)dst * 128 + 64 + lane * 2];  // hr[dst]
    float2 hl_d = __half22float2(*(__half2*)&rl);
    float2 hr   = __half22float2(*(__half2*)&rr);
    float2 a2 = *(const float2*)&att2[lane * 2];

    // self-loop
    float e0 = hl_d.x + hr.x; e0 = e0 > 0.f ? e0 : 0.2f * e0;
    float e1 = hl_d.y + hr.y; e1 = e1 > 0.f ? e1 : 0.2f * e1;
    float p = e0 * a2.x + e1 * a2.y;
#pragma unroll
    for (int off = 16; off >= 1; off >>= 1)
        p += __shfl_xor_sync(0xffffffffu, p, off);
    float m = p, den = 1.f;
    float2 acc = hl_d;

    int cnt = d_cur[dst];
    long base = (long)dst * SLOTS;
    int s = d_csrsrc[base];
    for (int i = 0; i < cnt; ++i) {
        int sn = d_csrsrc[base + i + 1];
        unsigned raw = *(const unsigned*)&d_buf2h[(size_t)s * 128 + lane * 2];
        float2 hl = __half22float2(*(__half2*)&raw);
        e0 = hl.x + hr.x; e0 = e0 > 0.f ? e0 : 0.2f * e0;
        e1 = hl.y + hr.y; e1 = e1 > 0.f ? e1 : 0.2f * e1;
        p = e0 * a2.x + e1 * a2.y;
#pragma unroll
        for (int off = 16; off >= 1; off >>= 1)
            p += __shfl_xor_sync(0xffffffffu, p, off);
        float nm = fmaxf(m, p);
        float sc = __expf(m - nm);
        float wgt = __expf(p - nm);
        den = den * sc + wgt;
        acc.x = acc.x * sc + wgt * hl.x;
        acc.y = acc.y * sc + wgt * hl.y;
        m = nm;
        s = sn;
    }
    float inv = 1.f / den;
    float o0 = acc.x * inv + b2[lane * 2];
    float o1 = acc.y * inv + b2[lane * 2 + 1];
    float mx = fmaxf(o0, o1);
#pragma unroll
    for (int off = 16; off >= 1; off >>= 1)
        mx = fmaxf(mx, __shfl_xor_sync(0xffffffffu, mx, off));
    float se = __expf(o0 - mx) + __expf(o1 - mx);
#pragma unroll
    for (int off = 16; off >= 1; off >>= 1)
        se += __shfl_xor_sync(0xffffffffu, se, off);
    float lse = mx + logf(se);
    out[(size_t)dst * 64 + lane * 2]     = o0 - lse;
    out[(size_t)dst * 64 + lane * 2 + 1] = o1 - lse;
}

// -------- launch (fork-join: scatter || GEMM1) --------
static cudaStream_t g_s1 = nullptr;
static cudaEvent_t  g_evA = nullptr, g_evB = nullptr;

extern "C" void kernel_launch(void* const* d_in, const int* in_sizes, int n_in,
                              void* d_out, int out_size) {
    const float* x    = (const float*)d_in[0];
    const int*   ei   = (const int*)d_in[1];
    const float* Wl1  = (const float*)d_in[2];
    const float* Wr1  = (const float*)d_in[3];
    const float* att1 = (const float*)d_in[4];
    const float* b1   = (const float*)d_in[5];
    const float* Wl2  = (const float*)d_in[6];
    const float* Wr2  = (const float*)d_in[7];
    const float* att2 = (const float*)d_in[8];
    const float* b2   = (const float*)d_in[9];
    float* out = (float*)d_out;

    if (!g_s1) {  // one-time host-object creation (no device memory)
        cudaStreamCreateWithFlags(&g_s1, cudaStreamNonBlocking);
        cudaEventCreateWithFlags(&g_evA, cudaEventDisableTiming);
        cudaEventCreateWithFlags(&g_evB, cudaEventDisableTiming);
    }

    __half *pBuf1h = nullptr, *pBuf2h = nullptr, *pH = nullptr;
    __half *pBt1 = nullptr, *pBt2 = nullptr;
    cudaGetSymbolAddress((void**)&pBuf1h, d_buf1h);
    cudaGetSymbolAddress((void**)&pH, d_H);
    cudaGetSymbolAddress((void**)&pBuf2h, d_buf2h);
    cudaGetSymbolAddress((void**)&pBt1, d_Bt1h);
    cudaGetSymbolAddress((void**)&pBt2, d_Bt2h);

    const int nb_nodes = (NN + 255) / 256;       // covers NN and 32768 transpose
    const int nb_edge4 = (EE / 4 + 255) / 256;   // 782

    // init: cursors = 0, weight transpose+fp16 convert
    k_init<<<nb_nodes, 256>>>(Wl1, Wr1, Wl2, Wr2);
    cudaEventRecord(g_evA, 0);

    // side stream: GEMM1 (needs Bt1 + x), concurrent with scatter
    cudaStreamWaitEvent(g_s1, g_evA, 0);
    {
        dim3 g1((NN + 127) / 128, 4);
        k_gemm_h<float><<<g1, 256, 0, g_s1>>>(x, pBt1, pBuf1h, NN, 256);
    }
    cudaEventRecord(g_evB, g_s1);

    // origin stream: direct adjacency scatter (no count/scan)
    k_scatter<<<nb_edge4, 256>>>(ei);

    // join, then layer 1 aggregate -> GEMM2 -> layer 2 aggregate
    cudaStreamWaitEvent(0, g_evB, 0);
    k_gat1<<<(NN + 7) / 8, 256>>>(att1, b1);
    {
        dim3 g2((NN + 127) / 128, 2);
        k_gemm_h<__half><<<g2, 256>>>(pH, pBt2, pBuf2h, NN, 128);
    }
    k_gat2<<<(NN + 7) / 8, 256>>>(att2, b2, out);
}